// round 2
// baseline (speedup 1.0000x reference)
#include <cuda_runtime.h>
#include <cuda_bf16.h>
#include <math.h>

#define NPTS 8192
#define CCH  128
#define KSEL 128
#define KNN  32

// ---------------- scratch (device globals; no allocation) ----------------
__device__ float  g_corr[(size_t)NPTS * NPTS];         // 256 MB
__device__ float  g_tcorr[NPTS * KSEL];
__device__ float  g_txyz[NPTS * KSEL * 3];
__device__ float  g_vfeat[108 * NPTS];
__device__ float  g_vcorr[NPTS * 27];
__device__ float  g_vxyz[NPTS * 27 * 3];
__device__ float  g_kin[NPTS * KNN * 4];
__device__ float  g_hout[128 * NPTS];

__device__ double g_vox_sum[8],  g_vox_sum2[8];
__device__ double g_knn_sum[8],  g_knn_sum2[8];
__device__ double g_out_sum[8],  g_out_sum2[8];
__device__ float  g_vox_mu[8], g_vox_inv[8];
__device__ float  g_knn_mu[8], g_knn_inv[8];
__device__ float  g_out_mu[8], g_out_inv[8];

// ---------------- helpers ----------------
__device__ __forceinline__ unsigned f2ord(float f) {
    unsigned u = __float_as_uint(f);
    return (u & 0x80000000u) ? ~u : (u | 0x80000000u);
}
__device__ __forceinline__ float ord2f(unsigned o) {
    return (o & 0x80000000u) ? __uint_as_float(o & 0x7FFFFFFFu)
                             : __uint_as_float(~o);
}

// ---------------- K0: zero the stat accumulators (graph replays!) ----------------
__global__ void zero_stats_kernel() {
    int t = threadIdx.x;
    if (t < 8) {
        g_vox_sum[t] = 0.0; g_vox_sum2[t] = 0.0;
        g_knn_sum[t] = 0.0; g_knn_sum2[t] = 0.0;
        g_out_sum[t] = 0.0; g_out_sum2[t] = 0.0;
    }
}

// ---------------- K1: correlation GEMM  corr[n][m] = dot(f1[:,n], f2[:,m]) / sqrt(128)
#define BM 64
#define BN 64
#define BK 16
__global__ void gemm_corr_kernel(const float* __restrict__ f1,
                                 const float* __restrict__ f2) {
    __shared__ float As[BK][BM];
    __shared__ float Bs[BK][BN];
    int bm = blockIdx.y * BM;
    int bn = blockIdx.x * BN;
    int t  = threadIdx.x;          // 256 threads
    int tr = t / 16, tc = t % 16;  // 16x16, 4x4 micro-tile each

    float acc[4][4];
#pragma unroll
    for (int i = 0; i < 4; i++)
#pragma unroll
        for (int j = 0; j < 4; j++) acc[i][j] = 0.f;

    for (int k0 = 0; k0 < CCH; k0 += BK) {
        for (int i = t; i < BK * BM; i += 256) {
            int kk = i / BM, nn = i % BM;
            As[kk][nn] = f1[(size_t)(k0 + kk) * NPTS + bm + nn];
        }
        for (int i = t; i < BK * BN; i += 256) {
            int kk = i / BN, nn = i % BN;
            Bs[kk][nn] = f2[(size_t)(k0 + kk) * NPTS + bn + nn];
        }
        __syncthreads();
#pragma unroll
        for (int kk = 0; kk < BK; kk++) {
            float a[4], b[4];
#pragma unroll
            for (int i = 0; i < 4; i++) a[i] = As[kk][tr * 4 + i];
#pragma unroll
            for (int j = 0; j < 4; j++) b[j] = Bs[kk][tc * 4 + j];
#pragma unroll
            for (int i = 0; i < 4; i++)
#pragma unroll
                for (int j = 0; j < 4; j++) acc[i][j] += a[i] * b[j];
        }
        __syncthreads();
    }
    const float scale = 0.088388347648318447f;  // 1/sqrt(128)
#pragma unroll
    for (int i = 0; i < 4; i++)
#pragma unroll
        for (int j = 0; j < 4; j++)
            g_corr[(size_t)(bm + tr * 4 + i) * NPTS + bn + tc * 4 + j] = acc[i][j] * scale;
}

// ---------------- K2: per-row top-128 (exact radix select) + xyz gather -----------
__global__ void topk_kernel(const float* __restrict__ xyz2) {
    __shared__ unsigned s_key[NPTS];
    __shared__ unsigned s_hist[256];
    __shared__ unsigned s_prefix, s_rem, s_cgt, s_ceq;

    int n = blockIdx.x;
    int t = threadIdx.x;  // 256
    const float* row = g_corr + (size_t)n * NPTS;

    for (int i = t; i < NPTS; i += 256) s_key[i] = f2ord(row[i]);
    if (t == 0) { s_prefix = 0; s_rem = KSEL; }
    __syncthreads();

    for (int p = 3; p >= 0; p--) {
        if (t < 256) s_hist[t] = 0;
        __syncthreads();
        unsigned prefix = s_prefix;
        unsigned rem    = s_rem;
        int hb = (p + 1) * 8;
        for (int i = t; i < NPTS; i += 256) {
            unsigned k = s_key[i];
            if (p == 3 || (k >> hb) == prefix)
                atomicAdd(&s_hist[(k >> (8 * p)) & 0xFFu], 1u);
        }
        __syncthreads();
        if (t == 0) {
            unsigned cum = 0;
            for (int b = 255; b >= 0; b--) {
                unsigned h = s_hist[b];
                if (cum + h >= rem) {
                    s_rem    = rem - cum;
                    s_prefix = (prefix << 8) | (unsigned)b;
                    break;
                }
                cum += h;
            }
        }
        __syncthreads();
    }
    if (t == 0) { s_cgt = 0; s_ceq = 0; }
    __syncthreads();
    unsigned T   = s_prefix;
    unsigned rem = s_rem;
    unsigned ngt = KSEL - rem;
    for (int i = t; i < NPTS; i += 256) {
        unsigned k = s_key[i];
        int slot = -1;
        if (k > T) {
            slot = (int)atomicAdd(&s_cgt, 1u);
        } else if (k == T) {
            unsigned e = atomicAdd(&s_ceq, 1u);
            if (e < rem) slot = (int)(ngt + e);
        }
        if (slot >= 0) {
            g_tcorr[(size_t)n * KSEL + slot] = ord2f(k);
            size_t o = ((size_t)n * KSEL + slot) * 3;
            g_txyz[o + 0] = xyz2[(size_t)i * 3 + 0];
            g_txyz[o + 1] = xyz2[(size_t)i * 3 + 1];
            g_txyz[o + 2] = xyz2[(size_t)i * 3 + 2];
        }
    }
}

// ---------------- K3: per-point voxel levels + coarse stage + knn select + GN stats
__global__ void pointfeat_kernel(const float* __restrict__ coords,
                                 const float* __restrict__ vw1, const float* __restrict__ vb1,
                                 const float* __restrict__ kw1, const float* __restrict__ kb1) {
    __shared__ float s_c[KSEL];
    __shared__ float s_x[KSEL][3];
    __shared__ float s_coord[3];
    __shared__ float s_add[27], s_cnt[27];
    __shared__ unsigned long long s_center[28];
    __shared__ float s_mv[27][3];
    __shared__ int   s_oob[27];
    __shared__ float s_cadd[28], s_ccnt[28];
    __shared__ float s_vcorr[27];
    __shared__ unsigned long long s_sort[KSEL];
    __shared__ float s_kin[KNN][4];
    __shared__ float s_gs[8], s_gs2[8], s_kgs[8], s_kgs2[8];
    __shared__ unsigned long long s_top1key;

    int n = blockIdx.x;
    int t = threadIdx.x;  // 128

    s_c[t] = g_tcorr[(size_t)n * KSEL + t];
    {
        size_t o = ((size_t)n * KSEL + t) * 3;
        s_x[t][0] = g_txyz[o + 0];
        s_x[t][1] = g_txyz[o + 1];
        s_x[t][2] = g_txyz[o + 2];
    }
    if (t < 3) s_coord[t] = coords[(size_t)n * 3 + t];
    if (t == 0) s_top1key = 0ull;
    __syncthreads();
    float c0 = s_coord[0], c1 = s_coord[1], c2 = s_coord[2];
    float x0 = s_x[t][0], x1 = s_x[t][1], x2 = s_x[t][2];

    // top-1 element of the row (reference's topk-order element 0) for oob bins
    {
        unsigned long long key =
            ((unsigned long long)f2ord(s_c[t]) << 32) | (unsigned)(127 - t);
        atomicMax(&s_top1key, key);
    }

    // --- 3 average-pool levels ---
    for (int lev = 0; lev < 3; lev++) {
        if (t < 27) { s_add[t] = 0.f; s_cnt[t] = 0.f; }
        __syncthreads();
        float r  = 0.25f * (float)(1 << lev);
        float d0 = rintf((x0 - c0) / r);
        float d1 = rintf((x1 - c1) / r);
        float d2 = rintf((x2 - c2) / r);
        if (fabsf(d0) <= 1.0f && fabsf(d1) <= 1.0f && fabsf(d2) <= 1.0f) {
            int cube = (int)((d0 + 1.f) * 9.f + (d1 + 1.f) * 3.f + (d2 + 1.f));
            atomicAdd(&s_add[cube], s_c[t]);
            atomicAdd(&s_cnt[cube], 1.f);
        }
        __syncthreads();
        if (t < 27)
            g_vfeat[(size_t)(lev * 27 + t) * NPTS + n] = s_add[t] / fmaxf(s_cnt[t], 1.f);
        __syncthreads();
    }

    // --- coarse scatter-max (R = 4, r = 2) ---
    if (t < 28) s_center[t] = 0ull;
    __syncthreads();
    {
        float d0 = rintf((x0 - c0) / 4.0f);
        float d1 = rintf((x1 - c1) / 4.0f);
        float d2 = rintf((x2 - c2) / 4.0f);
        if (fabsf(d0) <= 1.5f && fabsf(d1) <= 1.5f && fabsf(d2) <= 1.5f) {
            int b = (int)((d0 + 1.f) * 9.f + (d1 + 1.f) * 3.f + (d2 + 1.f)) + 1;
            unsigned long long key =
                ((unsigned long long)f2ord(s_c[t]) << 32) | (unsigned)(127 - t);
            atomicMax(&s_center[b], key);
        }
    }
    __syncthreads();
    int top1 = 127 - (int)(s_top1key & 0xFFFFFFFFu);
    if (t < 27) {
        unsigned long long k = s_center[t + 1];
        int oob, idx;
        if (k == 0ull) { oob = 1; idx = top1; }
        else {
            float v = ord2f((unsigned)(k >> 32));
            oob = (v <= 0.f);
            idx = oob ? top1 : (127 - (int)(k & 0xFFFFFFFFu));
        }
        s_oob[t] = oob;
        float cc0 = s_x[idx][0], cc1 = s_x[idx][1], cc2 = s_x[idx][2];
        float bx = (float)((t / 9) % 3 - 1);
        float by = (float)((t / 3) % 3 - 1);
        float bz = (float)(t % 3 - 1);
        float vk0 = c0 + bx * 4.f, vk1 = c1 + by * 4.f, vk2 = c2 + bz * 4.f;
        float m0 = fminf(fmaxf(cc0 - vk0, -1.f), 1.f) + vk0;
        float m1 = fminf(fmaxf(cc1 - vk1, -1.f), 1.f) + vk1;
        float m2 = fminf(fmaxf(cc2 - vk2, -1.f), 1.f) + vk2;
        s_mv[t][0] = m0; s_mv[t][1] = m1; s_mv[t][2] = m2;
        size_t o = ((size_t)n * 27 + t) * 3;
        g_vxyz[o + 0] = m0; g_vxyz[o + 1] = m1; g_vxyz[o + 2] = m2;
    }
    if (t < 28) { s_cadd[t] = 0.f; s_ccnt[t] = 0.f; }
    if (t < 8)  { s_gs[t] = 0.f; s_gs2[t] = 0.f; s_kgs[t] = 0.f; s_kgs2[t] = 0.f; }
    __syncthreads();
    {
        int idx = 27;
        for (int k = 0; k < 27; k++) {
            if (!s_oob[k]) {
                if (fabsf((x0 - s_mv[k][0]) / 2.0f) <= 0.5f &&
                    fabsf((x1 - s_mv[k][1]) / 2.0f) <= 0.5f &&
                    fabsf((x2 - s_mv[k][2]) / 2.0f) <= 0.5f)
                    idx = k;
            }
        }
        atomicAdd(&s_cadd[idx], s_c[t]);
        atomicAdd(&s_ccnt[idx], 1.f);
    }
    __syncthreads();
    if (t < 27) {
        float vc = s_cadd[t] / fmaxf(s_ccnt[t], 1.f);
        s_vcorr[t] = vc;
        g_vcorr[(size_t)n * 27 + t] = vc;
    }
    __syncthreads();

    // --- vox branch conv1 stats (8 groups x 4ch, over 27 voxels) ---
    for (int i = t; i < 32 * 27; i += 128) {
        int ch = i / 27, k = i % 27;
        float h = vw1[ch * 4 + 0] * s_vcorr[k] + vw1[ch * 4 + 1] * s_mv[k][0]
                + vw1[ch * 4 + 2] * s_mv[k][1] + vw1[ch * 4 + 3] * s_mv[k][2] + vb1[ch];
        atomicAdd(&s_gs[ch >> 2], h);
        atomicAdd(&s_gs2[ch >> 2], h * h);
    }

    // --- knn select: 32 nearest of 128 via bitonic sort ---
    {
        float dx = x0 - c0, dy = x1 - c1, dz = x2 - c2;
        float dd = dx * dx + dy * dy + dz * dz;
        s_sort[t] = ((unsigned long long)__float_as_uint(dd) << 32) | (unsigned)t;
    }
    for (int size = 2; size <= 128; size <<= 1)
        for (int stride = size >> 1; stride > 0; stride >>= 1) {
            __syncthreads();
            int p = t ^ stride;
            if (p > t) {
                bool up = ((t & size) == 0);
                unsigned long long a = s_sort[t], b = s_sort[p];
                if ((a > b) == up) { s_sort[t] = b; s_sort[p] = a; }
            }
        }
    __syncthreads();
    if (t < KNN) {
        int j = (int)(s_sort[t] & 0xFFFFFFFFu);
        float kc = s_c[j];
        float k0 = s_x[j][0] - c0, k1 = s_x[j][1] - c1, k2 = s_x[j][2] - c2;
        s_kin[t][0] = kc; s_kin[t][1] = k0; s_kin[t][2] = k1; s_kin[t][3] = k2;
        size_t o = ((size_t)n * KNN + t) * 4;
        g_kin[o] = kc; g_kin[o + 1] = k0; g_kin[o + 2] = k1; g_kin[o + 3] = k2;
    }
    __syncthreads();
    // --- knn conv1 stats (8 groups x 8ch over 32 nbrs) ---
    for (int i = t; i < 64 * KNN; i += 128) {
        int ch = i >> 5, s = i & 31;
        float h = kw1[ch * 4 + 0] * s_kin[s][0] + kw1[ch * 4 + 1] * s_kin[s][1]
                + kw1[ch * 4 + 2] * s_kin[s][2] + kw1[ch * 4 + 3] * s_kin[s][3] + kb1[ch];
        atomicAdd(&s_kgs[ch >> 3], h);
        atomicAdd(&s_kgs2[ch >> 3], h * h);
    }
    __syncthreads();
    if (t < 8) {
        atomicAdd(&g_vox_sum[t],  (double)s_gs[t]);
        atomicAdd(&g_vox_sum2[t], (double)s_gs2[t]);
        atomicAdd(&g_knn_sum[t],  (double)s_kgs[t]);
        atomicAdd(&g_knn_sum2[t], (double)s_kgs2[t]);
    }
}

// ---------------- K4: finalize vox + knn GN stats ----------------
__global__ void finalize_vk_kernel() {
    int t = threadIdx.x;
    if (t < 8) {
        double cnt = 4.0 * NPTS * 27.0;
        double mu  = g_vox_sum[t] / cnt;
        double var = g_vox_sum2[t] / cnt - mu * mu;
        g_vox_mu[t]  = (float)mu;
        g_vox_inv[t] = (float)(1.0 / sqrt(var + 1e-5));
    } else if (t < 16) {
        int g = t - 8;
        double cnt = 8.0 * NPTS * (double)KNN;
        double mu  = g_knn_sum[g] / cnt;
        double var = g_knn_sum2[g] / cnt - mu * mu;
        g_knn_mu[g]  = (float)mu;
        g_knn_inv[g] = (float)(1.0 / sqrt(var + 1e-5));
    }
}

// ---------------- K5: vox MLP apply -> vfeat channels 81..107 ----------------
__global__ void vox_apply_kernel(const float* __restrict__ w1, const float* __restrict__ b1,
                                 const float* __restrict__ gma, const float* __restrict__ bta,
                                 const float* __restrict__ pr, const float* __restrict__ w2,
                                 const float* __restrict__ b2) {
    int idx = blockIdx.x * blockDim.x + threadIdx.x;
    if (idx >= NPTS * 27) return;
    int n = idx / 27, k = idx % 27;
    float vc = g_vcorr[idx];
    float m0 = g_vxyz[(size_t)idx * 3 + 0];
    float m1 = g_vxyz[(size_t)idx * 3 + 1];
    float m2 = g_vxyz[(size_t)idx * 3 + 2];
    float a = pr[0];
    float acc = b2[0];
#pragma unroll
    for (int ch = 0; ch < 32; ch++) {
        float h = w1[ch * 4 + 0] * vc + w1[ch * 4 + 1] * m0
                + w1[ch * 4 + 2] * m1 + w1[ch * 4 + 3] * m2 + b1[ch];
        int gr = ch >> 2;
        h = (h - g_vox_mu[gr]) * g_vox_inv[gr] * gma[ch] + bta[ch];
        h = (h >= 0.f) ? h : a * h;
        acc += w2[ch] * h;
    }
    g_vfeat[(size_t)(81 + k) * NPTS + n] = acc;
}

// ---------------- K6: out conv1 (128 x 108) + GN stats ----------------
__global__ void out_conv1_kernel(const float* __restrict__ w1, const float* __restrict__ b1) {
    __shared__ float vt[108][64];
    int n0 = blockIdx.x * 64;
    int o  = threadIdx.x;  // 128
    for (int i = threadIdx.x; i < 108 * 64; i += 128) {
        int c = i / 64, nn = i % 64;
        vt[c][nn] = g_vfeat[(size_t)c * NPTS + n0 + nn];
    }
    __syncthreads();
    float bo = b1[o];
    float lsf = 0.f, ls2f = 0.f;
    for (int nb = 0; nb < 64; nb += 8) {
        float acc[8];
#pragma unroll
        for (int q = 0; q < 8; q++) acc[q] = bo;
        for (int c = 0; c < 108; c++) {
            float wv = __ldg(&w1[o * 108 + c]);
#pragma unroll
            for (int q = 0; q < 8; q++) acc[q] += wv * vt[c][nb + q];
        }
#pragma unroll
        for (int q = 0; q < 8; q++) {
            g_hout[(size_t)o * NPTS + n0 + nb + q] = acc[q];
            lsf  += acc[q];
            ls2f += acc[q] * acc[q];
        }
    }
    atomicAdd(&g_out_sum[o >> 4],  (double)lsf);
    atomicAdd(&g_out_sum2[o >> 4], (double)ls2f);
}

// ---------------- K7: finalize out GN stats ----------------
__global__ void finalize_out_kernel() {
    int t = threadIdx.x;
    if (t < 8) {
        double cnt = 16.0 * NPTS;
        double mu  = g_out_sum[t] / cnt;
        double var = g_out_sum2[t] / cnt - mu * mu;
        g_out_mu[t]  = (float)mu;
        g_out_inv[t] = (float)(1.0 / sqrt(var + 1e-5));
    }
}

// ---------------- K8: out GN+prelu + conv2 (64 x 128) -> d_out ----------------
__global__ void out_apply_kernel(const float* __restrict__ gma, const float* __restrict__ bta,
                                 const float* __restrict__ pr, const float* __restrict__ w2,
                                 const float* __restrict__ b2, float* __restrict__ out) {
    __shared__ float act[128][64];
    int n0 = blockIdx.x * 64;
    int t  = threadIdx.x;  // 256
    float a = pr[0];
    for (int i = t; i < 128 * 64; i += 256) {
        int ch = i / 64, nn = i % 64;
        float x = g_hout[(size_t)ch * NPTS + n0 + nn];
        int gr = ch >> 4;
        x = (x - g_out_mu[gr]) * g_out_inv[gr] * gma[ch] + bta[ch];
        act[ch][nn] = (x >= 0.f) ? x : a * x;
    }
    __syncthreads();
    for (int i = t; i < 64 * 64; i += 256) {
        int o = i / 64, nn = i % 64;
        float acc = b2[o];
        for (int c = 0; c < 128; c++) acc += w2[o * 128 + c] * act[c][nn];
        out[(size_t)o * NPTS + n0 + nn] = acc;
    }
}

// ---------------- K9: knn GN+prelu+max + conv (64x64), add into d_out ----------
__global__ void knn_apply_kernel(const float* __restrict__ w1, const float* __restrict__ b1,
                                 const float* __restrict__ gma, const float* __restrict__ bta,
                                 const float* __restrict__ pr, const float* __restrict__ ow,
                                 const float* __restrict__ ob, float* __restrict__ out) {
    __shared__ float s_kf[64];
    __shared__ float s_kin[KNN][4];
    int n = blockIdx.x;
    int t = threadIdx.x;  // 64
    for (int i = t; i < KNN * 4; i += 64)
        s_kin[i / 4][i % 4] = g_kin[(size_t)n * KNN * 4 + i];
    __syncthreads();
    {
        int ch = t;
        float a = pr[0];
        float w0 = w1[ch * 4 + 0], w1_ = w1[ch * 4 + 1], w2_ = w1[ch * 4 + 2], w3_ = w1[ch * 4 + 3];
        float bb = b1[ch];
        float mu = g_knn_mu[ch >> 3], inv = g_knn_inv[ch >> 3];
        float gg = gma[ch], bt_ = bta[ch];
        float mx = -INFINITY;
#pragma unroll
        for (int s = 0; s < KNN; s++) {
            float h = w0 * s_kin[s][0] + w1_ * s_kin[s][1] + w2_ * s_kin[s][2] + w3_ * s_kin[s][3] + bb;
            h = (h - mu) * inv * gg + bt_;
            h = (h >= 0.f) ? h : a * h;
            mx = fmaxf(mx, h);
        }
        s_kf[ch] = mx;
    }
    __syncthreads();
    {
        int o = t;
        float acc = ob[o];
#pragma unroll
        for (int c = 0; c < 64; c++) acc += ow[o * 64 + c] * s_kf[c];
        out[(size_t)o * NPTS + n] += acc;
    }
}

// ---------------- launch ----------------
extern "C" void kernel_launch(void* const* d_in, const int* in_sizes, int n_in,
                              void* d_out, int out_size) {
    const float* fmap1  = (const float*)d_in[0];
    const float* fmap2  = (const float*)d_in[1];
    const float* xyz2   = (const float*)d_in[2];
    const float* coords = (const float*)d_in[3];
    const float* out_w1 = (const float*)d_in[4];
    const float* out_b1 = (const float*)d_in[5];
    const float* out_g  = (const float*)d_in[6];
    const float* out_bt = (const float*)d_in[7];
    const float* out_pr = (const float*)d_in[8];
    const float* out_w2 = (const float*)d_in[9];
    const float* out_b2 = (const float*)d_in[10];
    const float* vox_w1 = (const float*)d_in[11];
    const float* vox_b1 = (const float*)d_in[12];
    const float* vox_g  = (const float*)d_in[13];
    const float* vox_bt = (const float*)d_in[14];
    const float* vox_pr = (const float*)d_in[15];
    const float* vox_w2 = (const float*)d_in[16];
    const float* vox_b2 = (const float*)d_in[17];
    const float* knn_w1 = (const float*)d_in[18];
    const float* knn_b1 = (const float*)d_in[19];
    const float* knn_g  = (const float*)d_in[20];
    const float* knn_bt = (const float*)d_in[21];
    const float* knn_pr = (const float*)d_in[22];
    const float* knn_ow = (const float*)d_in[23];
    const float* knn_ob = (const float*)d_in[24];
    float* out = (float*)d_out;

    zero_stats_kernel<<<1, 32>>>();
    gemm_corr_kernel<<<dim3(NPTS / BN, NPTS / BM), 256>>>(fmap1, fmap2);
    topk_kernel<<<NPTS, 256>>>(xyz2);
    pointfeat_kernel<<<NPTS, 128>>>(coords, vox_w1, vox_b1, knn_w1, knn_b1);
    finalize_vk_kernel<<<1, 32>>>();
    vox_apply_kernel<<<(NPTS * 27 + 255) / 256, 256>>>(vox_w1, vox_b1, vox_g, vox_bt,
                                                       vox_pr, vox_w2, vox_b2);
    out_conv1_kernel<<<NPTS / 64, 128>>>(out_w1, out_b1);
    finalize_out_kernel<<<1, 32>>>();
    out_apply_kernel<<<NPTS / 64, 256>>>(out_g, out_bt, out_pr, out_w2, out_b2, out);
    knn_apply_kernel<<<NPTS, 64>>>(knn_w1, knn_b1, knn_g, knn_bt, knn_pr,
                                   knn_ow, knn_ob, out);
}

// round 3
// speedup vs baseline: 2.0811x; 2.0811x over previous
#include <cuda_runtime.h>
#include <cuda_bf16.h>
#include <math.h>

#define NPTS 8192
#define CCH  128
#define KSEL 128
#define KNN  32

// ---------------- scratch (device globals; no allocation) ----------------
__device__ float  g_corr[(size_t)NPTS * NPTS];         // 256 MB
__device__ float  g_tcorr[NPTS * KSEL];
__device__ float  g_txyz[NPTS * KSEL * 3];
__device__ float  g_vfeat[108 * NPTS];
__device__ float  g_vcorr[NPTS * 27];
__device__ float  g_vxyz[NPTS * 27 * 3];
__device__ float  g_kin[NPTS * KNN * 4];
__device__ float  g_hout[128 * NPTS];

__device__ double g_vox_sum[8],  g_vox_sum2[8];
__device__ double g_knn_sum[8],  g_knn_sum2[8];
__device__ double g_out_sum[8],  g_out_sum2[8];
__device__ float  g_vox_mu[8], g_vox_inv[8];
__device__ float  g_knn_mu[8], g_knn_inv[8];
__device__ float  g_out_mu[8], g_out_inv[8];

// ---------------- helpers ----------------
__device__ __forceinline__ unsigned f2ord(float f) {
    unsigned u = __float_as_uint(f);
    return (u & 0x80000000u) ? ~u : (u | 0x80000000u);
}
__device__ __forceinline__ float ord2f(unsigned o) {
    return (o & 0x80000000u) ? __uint_as_float(o & 0x7FFFFFFFu)
                             : __uint_as_float(~o);
}

// ---------------- K0: zero the stat accumulators (graph replays!) ----------------
__global__ void zero_stats_kernel() {
    int t = threadIdx.x;
    if (t < 8) {
        g_vox_sum[t] = 0.0; g_vox_sum2[t] = 0.0;
        g_knn_sum[t] = 0.0; g_knn_sum2[t] = 0.0;
        g_out_sum[t] = 0.0; g_out_sum2[t] = 0.0;
    }
}

// ---------------- K1: correlation GEMM  corr[n][m] = dot(f1[:,n], f2[:,m]) / sqrt(128)
#define GBM 128
#define GBN 128
#define GBK 8
__global__ __launch_bounds__(256) void gemm_corr_kernel(const float* __restrict__ f1,
                                                        const float* __restrict__ f2) {
    __shared__ float As[GBK][GBM];
    __shared__ float Bs[GBK][GBN];
    int bm = blockIdx.y * GBM;
    int bn = blockIdx.x * GBN;
    int t  = threadIdx.x;          // 256 threads
    int tr = t >> 4, tc = t & 15;  // 16x16, 8x8 micro-tile

    float acc[8][8];
#pragma unroll
    for (int i = 0; i < 8; i++)
#pragma unroll
        for (int j = 0; j < 8; j++) acc[i][j] = 0.f;

    int lrow  = t >> 5;            // 0..7
    int lcol4 = (t & 31) << 2;     // 0..124 step 4

    for (int k0 = 0; k0 < CCH; k0 += GBK) {
        *(float4*)&As[lrow][lcol4] = *(const float4*)&f1[(size_t)(k0 + lrow) * NPTS + bm + lcol4];
        *(float4*)&Bs[lrow][lcol4] = *(const float4*)&f2[(size_t)(k0 + lrow) * NPTS + bn + lcol4];
        __syncthreads();
#pragma unroll
        for (int kk = 0; kk < GBK; kk++) {
            float a[8], b[8];
            *(float4*)&a[0] = *(float4*)&As[kk][tr * 8];
            *(float4*)&a[4] = *(float4*)&As[kk][tr * 8 + 4];
            *(float4*)&b[0] = *(float4*)&Bs[kk][tc * 8];
            *(float4*)&b[4] = *(float4*)&Bs[kk][tc * 8 + 4];
#pragma unroll
            for (int i = 0; i < 8; i++)
#pragma unroll
                for (int j = 0; j < 8; j++) acc[i][j] += a[i] * b[j];
        }
        __syncthreads();
    }
    const float scale = 0.088388347648318447f;  // 1/sqrt(128)
#pragma unroll
    for (int i = 0; i < 8; i++) {
        float4 v0, v1;
        v0.x = acc[i][0] * scale; v0.y = acc[i][1] * scale;
        v0.z = acc[i][2] * scale; v0.w = acc[i][3] * scale;
        v1.x = acc[i][4] * scale; v1.y = acc[i][5] * scale;
        v1.z = acc[i][6] * scale; v1.w = acc[i][7] * scale;
        size_t o = (size_t)(bm + tr * 8 + i) * NPTS + bn + tc * 8;
        *(float4*)&g_corr[o]     = v0;
        *(float4*)&g_corr[o + 4] = v1;
    }
}

// ---------------- K2: per-row top-128 (radix prefix + candidate rank) -------------
__global__ __launch_bounds__(256) void topk_kernel(const float* __restrict__ xyz2) {
    __shared__ unsigned s_key[NPTS];                 // 32 KB
    __shared__ unsigned s_whist[4][256];             // 4 KB (per-warp-pair hist)
    __shared__ unsigned s_hist[256];                 // 1 KB
    __shared__ unsigned long long s_cand[1024];      // 8 KB
    __shared__ unsigned s_b1, s_rem, s_cgt, s_ccnt;

    int n = blockIdx.x;
    int t = threadIdx.x;  // 256
    int w2 = t >> 6;      // warp-pair 0..3
    const float* rowp = g_corr + (size_t)n * NPTS;

    for (int i = t; i < 4 * 256; i += 256) ((unsigned*)s_whist)[i] = 0;
    __syncthreads();

    // scan A: global load + keys + 8-bit hist
    for (int i = t; i < NPTS; i += 256) {
        unsigned k = f2ord(rowp[i]);
        s_key[i] = k;
        atomicAdd(&s_whist[w2][k >> 24], 1u);
    }
    __syncthreads();
    {
        unsigned sum = s_whist[0][t] + s_whist[1][t] + s_whist[2][t] + s_whist[3][t];
        s_hist[t] = sum;
    }
    __syncthreads();
    if (t == 0) {
        unsigned cum = 0;
        for (int b = 255; b >= 0; b--) {
            unsigned h = s_hist[b];
            if (cum + h >= KSEL) { s_b1 = (unsigned)b; s_rem = KSEL - cum; break; }
            cum += h;
        }
    }
    __syncthreads();
    unsigned b1 = s_b1;
    s_hist[t] = 0;
    __syncthreads();
    // scan B: hist of bits[16:24) within bucket b1 (few hits)
    for (int i = t; i < NPTS; i += 256) {
        unsigned k = s_key[i];
        if ((k >> 24) == b1) atomicAdd(&s_hist[(k >> 16) & 0xFFu], 1u);
    }
    __syncthreads();
    if (t == 0) {
        unsigned rem = s_rem, cum = 0;
        for (int b = 255; b >= 0; b--) {
            unsigned h = s_hist[b];
            if (cum + h >= rem) { s_b1 = (b1 << 8) | (unsigned)b; s_rem = rem - cum; break; }
            cum += h;
        }
        s_cgt = 0; s_ccnt = 0;
    }
    __syncthreads();
    unsigned p16 = s_b1;
    unsigned rem = s_rem;
    unsigned ngt = KSEL - rem;
    // scan C: direct-emit clear winners, compact boundary candidates
    for (int i = t; i < NPTS; i += 256) {
        unsigned k   = s_key[i];
        unsigned t16 = k >> 16;
        if (t16 > p16) {
            unsigned slot = atomicAdd(&s_cgt, 1u);
            g_tcorr[(size_t)n * KSEL + slot] = ord2f(k);
            size_t o = ((size_t)n * KSEL + slot) * 3;
            g_txyz[o + 0] = xyz2[(size_t)i * 3 + 0];
            g_txyz[o + 1] = xyz2[(size_t)i * 3 + 1];
            g_txyz[o + 2] = xyz2[(size_t)i * 3 + 2];
        } else if (t16 == p16) {
            unsigned ci = atomicAdd(&s_ccnt, 1u);
            if (ci < 1024u)
                s_cand[ci] = ((unsigned long long)k << 13) | (unsigned long long)(8191u - (unsigned)i);
        }
    }
    __syncthreads();
    unsigned C = min(s_ccnt, 1024u);
    // rank the (small) candidate set: key desc, original index asc
    for (unsigned i = t; i < C; i += 256) {
        unsigned long long wi = s_cand[i];
        unsigned r = 0;
        for (unsigned j = 0; j < C; j++) r += (s_cand[j] > wi) ? 1u : 0u;
        if (r < rem) {
            unsigned slot = ngt + r;
            unsigned k  = (unsigned)(wi >> 13);
            unsigned oi = 8191u - (unsigned)(wi & 8191ull);
            g_tcorr[(size_t)n * KSEL + slot] = ord2f(k);
            size_t o = ((size_t)n * KSEL + slot) * 3;
            g_txyz[o + 0] = xyz2[(size_t)oi * 3 + 0];
            g_txyz[o + 1] = xyz2[(size_t)oi * 3 + 1];
            g_txyz[o + 2] = xyz2[(size_t)oi * 3 + 2];
        }
    }
}

// ---------------- K3: per-point voxel levels + coarse stage + knn select + GN stats
__global__ __launch_bounds__(128) void pointfeat_kernel(const float* __restrict__ coords,
                                 const float* __restrict__ vw1, const float* __restrict__ vb1,
                                 const float* __restrict__ kw1, const float* __restrict__ kb1) {
    __shared__ float s_c[KSEL];
    __shared__ float s_x[KSEL][3];
    __shared__ float s_dd[KSEL];
    __shared__ float s_coord[3];
    __shared__ float s_add[27], s_cnt[27];
    __shared__ unsigned long long s_center[28];
    __shared__ float s_mv[27][3];
    __shared__ int   s_oob[27];
    __shared__ float s_cadd[28], s_ccnt[28];
    __shared__ float s_vcorr[27];
    __shared__ float s_kin[KNN][4];
    __shared__ float s_gs[8], s_gs2[8], s_kgs[8], s_kgs2[8];
    __shared__ unsigned long long s_top1key;

    int n = blockIdx.x;
    int t = threadIdx.x;  // 128

    s_c[t] = g_tcorr[(size_t)n * KSEL + t];
    {
        size_t o = ((size_t)n * KSEL + t) * 3;
        s_x[t][0] = g_txyz[o + 0];
        s_x[t][1] = g_txyz[o + 1];
        s_x[t][2] = g_txyz[o + 2];
    }
    if (t < 3) s_coord[t] = coords[(size_t)n * 3 + t];
    if (t == 0) s_top1key = 0ull;
    __syncthreads();
    float c0 = s_coord[0], c1 = s_coord[1], c2 = s_coord[2];
    float x0 = s_x[t][0], x1 = s_x[t][1], x2 = s_x[t][2];

    // distances + row-top1 (value argmax for oob bins)
    {
        float dx = x0 - c0, dy = x1 - c1, dz = x2 - c2;
        s_dd[t] = dx * dx + dy * dy + dz * dz;
        unsigned long long key =
            ((unsigned long long)f2ord(s_c[t]) << 32) | (unsigned)(127 - t);
        atomicMax(&s_top1key, key);
    }

    // --- 3 average-pool levels ---
    for (int lev = 0; lev < 3; lev++) {
        if (t < 27) { s_add[t] = 0.f; s_cnt[t] = 0.f; }
        __syncthreads();
        float r  = 0.25f * (float)(1 << lev);
        float d0 = rintf((x0 - c0) / r);
        float d1 = rintf((x1 - c1) / r);
        float d2 = rintf((x2 - c2) / r);
        if (fabsf(d0) <= 1.0f && fabsf(d1) <= 1.0f && fabsf(d2) <= 1.0f) {
            int cube = (int)((d0 + 1.f) * 9.f + (d1 + 1.f) * 3.f + (d2 + 1.f));
            atomicAdd(&s_add[cube], s_c[t]);
            atomicAdd(&s_cnt[cube], 1.f);
        }
        __syncthreads();
        if (t < 27)
            g_vfeat[(size_t)(lev * 27 + t) * NPTS + n] = s_add[t] / fmaxf(s_cnt[t], 1.f);
        __syncthreads();
    }

    // --- coarse scatter-max (R = 4, r = 2) ---
    if (t < 28) s_center[t] = 0ull;
    __syncthreads();
    {
        float d0 = rintf((x0 - c0) / 4.0f);
        float d1 = rintf((x1 - c1) / 4.0f);
        float d2 = rintf((x2 - c2) / 4.0f);
        if (fabsf(d0) <= 1.5f && fabsf(d1) <= 1.5f && fabsf(d2) <= 1.5f) {
            int b = (int)((d0 + 1.f) * 9.f + (d1 + 1.f) * 3.f + (d2 + 1.f)) + 1;
            unsigned long long key =
                ((unsigned long long)f2ord(s_c[t]) << 32) | (unsigned)(127 - t);
            atomicMax(&s_center[b], key);
        }
    }
    __syncthreads();
    int top1 = 127 - (int)(s_top1key & 0xFFFFFFFFu);
    if (t < 27) {
        unsigned long long k = s_center[t + 1];
        int oob, idx;
        if (k == 0ull) { oob = 1; idx = top1; }
        else {
            float v = ord2f((unsigned)(k >> 32));
            oob = (v <= 0.f);
            idx = oob ? top1 : (127 - (int)(k & 0xFFFFFFFFu));
        }
        s_oob[t] = oob;
        float cc0 = s_x[idx][0], cc1 = s_x[idx][1], cc2 = s_x[idx][2];
        float bx = (float)((t / 9) % 3 - 1);
        float by = (float)((t / 3) % 3 - 1);
        float bz = (float)(t % 3 - 1);
        float vk0 = c0 + bx * 4.f, vk1 = c1 + by * 4.f, vk2 = c2 + bz * 4.f;
        float m0 = fminf(fmaxf(cc0 - vk0, -1.f), 1.f) + vk0;
        float m1 = fminf(fmaxf(cc1 - vk1, -1.f), 1.f) + vk1;
        float m2 = fminf(fmaxf(cc2 - vk2, -1.f), 1.f) + vk2;
        s_mv[t][0] = m0; s_mv[t][1] = m1; s_mv[t][2] = m2;
        size_t o = ((size_t)n * 27 + t) * 3;
        g_vxyz[o + 0] = m0; g_vxyz[o + 1] = m1; g_vxyz[o + 2] = m2;
    }
    if (t < 28) { s_cadd[t] = 0.f; s_ccnt[t] = 0.f; }
    __syncthreads();

    // idx_scatter + knn rank-select in the same phase
    {
        int idx = 27;
        for (int k = 0; k < 27; k++) {
            if (!s_oob[k]) {
                if (fabsf((x0 - s_mv[k][0]) / 2.0f) <= 0.5f &&
                    fabsf((x1 - s_mv[k][1]) / 2.0f) <= 0.5f &&
                    fabsf((x2 - s_mv[k][2]) / 2.0f) <= 0.5f)
                    idx = k;
            }
        }
        atomicAdd(&s_cadd[idx], s_c[t]);
        atomicAdd(&s_ccnt[idx], 1.f);
    }
    {
        float dd = s_dd[t];
        int r = 0;
#pragma unroll 8
        for (int j = 0; j < KSEL; j++) {
            float dj = s_dd[j];
            r += (dj < dd || (dj == dd && j < t)) ? 1 : 0;
        }
        if (r < KNN) {
            float kc = s_c[t];
            float k0 = x0 - c0, k1 = x1 - c1, k2 = x2 - c2;
            s_kin[r][0] = kc; s_kin[r][1] = k0; s_kin[r][2] = k1; s_kin[r][3] = k2;
            size_t o = ((size_t)n * KNN + r) * 4;
            g_kin[o] = kc; g_kin[o + 1] = k0; g_kin[o + 2] = k1; g_kin[o + 3] = k2;
        }
    }
    __syncthreads();
    if (t < 27) {
        float vc = s_cadd[t] / fmaxf(s_ccnt[t], 1.f);
        s_vcorr[t] = vc;
        g_vcorr[(size_t)n * 27 + t] = vc;
    }
    __syncthreads();

    // --- vox conv1 stats: threads 64..95, ch = t-64; segment-reduce over 4 lanes ---
    if (t >= 64 && t < 96) {
        int ch = t - 64;
        float w0 = vw1[ch * 4 + 0], w1_ = vw1[ch * 4 + 1];
        float w2_ = vw1[ch * 4 + 2], w3_ = vw1[ch * 4 + 3];
        float bb = vb1[ch];
        float sum = 0.f, sum2 = 0.f;
#pragma unroll
        for (int k = 0; k < 27; k++) {
            float h = w0 * s_vcorr[k] + w1_ * s_mv[k][0] + w2_ * s_mv[k][1] + w3_ * s_mv[k][2] + bb;
            sum += h; sum2 += h * h;
        }
        sum  += __shfl_xor_sync(0xFFFFFFFFu, sum, 1);
        sum2 += __shfl_xor_sync(0xFFFFFFFFu, sum2, 1);
        sum  += __shfl_xor_sync(0xFFFFFFFFu, sum, 2);
        sum2 += __shfl_xor_sync(0xFFFFFFFFu, sum2, 2);
        if ((ch & 3) == 0) { s_gs[ch >> 2] = sum; s_gs2[ch >> 2] = sum2; }
    }
    // --- knn conv1 stats: threads 0..63, ch = t; segment-reduce over 8 lanes ---
    if (t < 64) {
        int ch = t;
        float w0 = kw1[ch * 4 + 0], w1_ = kw1[ch * 4 + 1];
        float w2_ = kw1[ch * 4 + 2], w3_ = kw1[ch * 4 + 3];
        float bb = kb1[ch];
        float sum = 0.f, sum2 = 0.f;
#pragma unroll
        for (int s = 0; s < KNN; s++) {
            float h = w0 * s_kin[s][0] + w1_ * s_kin[s][1] + w2_ * s_kin[s][2] + w3_ * s_kin[s][3] + bb;
            sum += h; sum2 += h * h;
        }
        sum  += __shfl_xor_sync(0xFFFFFFFFu, sum, 1);
        sum2 += __shfl_xor_sync(0xFFFFFFFFu, sum2, 1);
        sum  += __shfl_xor_sync(0xFFFFFFFFu, sum, 2);
        sum2 += __shfl_xor_sync(0xFFFFFFFFu, sum2, 2);
        sum  += __shfl_xor_sync(0xFFFFFFFFu, sum, 4);
        sum2 += __shfl_xor_sync(0xFFFFFFFFu, sum2, 4);
        if ((ch & 7) == 0) { s_kgs[ch >> 3] = sum; s_kgs2[ch >> 3] = sum2; }
    }
    __syncthreads();
    if (t < 8) {
        atomicAdd(&g_vox_sum[t],  (double)s_gs[t]);
        atomicAdd(&g_vox_sum2[t], (double)s_gs2[t]);
        atomicAdd(&g_knn_sum[t],  (double)s_kgs[t]);
        atomicAdd(&g_knn_sum2[t], (double)s_kgs2[t]);
    }
}

// ---------------- K4: finalize vox + knn GN stats ----------------
__global__ void finalize_vk_kernel() {
    int t = threadIdx.x;
    if (t < 8) {
        double cnt = 4.0 * NPTS * 27.0;
        double mu  = g_vox_sum[t] / cnt;
        double var = g_vox_sum2[t] / cnt - mu * mu;
        g_vox_mu[t]  = (float)mu;
        g_vox_inv[t] = (float)(1.0 / sqrt(var + 1e-5));
    } else if (t < 16) {
        int g = t - 8;
        double cnt = 8.0 * NPTS * (double)KNN;
        double mu  = g_knn_sum[g] / cnt;
        double var = g_knn_sum2[g] / cnt - mu * mu;
        g_knn_mu[g]  = (float)mu;
        g_knn_inv[g] = (float)(1.0 / sqrt(var + 1e-5));
    }
}

// ---------------- K5: vox MLP apply -> vfeat channels 81..107 ----------------
__global__ void vox_apply_kernel(const float* __restrict__ w1, const float* __restrict__ b1,
                                 const float* __restrict__ gma, const float* __restrict__ bta,
                                 const float* __restrict__ pr, const float* __restrict__ w2,
                                 const float* __restrict__ b2) {
    int idx = blockIdx.x * blockDim.x + threadIdx.x;
    if (idx >= NPTS * 27) return;
    int n = idx / 27, k = idx % 27;
    float vc = g_vcorr[idx];
    float m0 = g_vxyz[(size_t)idx * 3 + 0];
    float m1 = g_vxyz[(size_t)idx * 3 + 1];
    float m2 = g_vxyz[(size_t)idx * 3 + 2];
    float a = pr[0];
    float acc = b2[0];
#pragma unroll
    for (int ch = 0; ch < 32; ch++) {
        float h = w1[ch * 4 + 0] * vc + w1[ch * 4 + 1] * m0
                + w1[ch * 4 + 2] * m1 + w1[ch * 4 + 3] * m2 + b1[ch];
        int gr = ch >> 2;
        h = (h - g_vox_mu[gr]) * g_vox_inv[gr] * gma[ch] + bta[ch];
        h = (h >= 0.f) ? h : a * h;
        acc += w2[ch] * h;
    }
    g_vfeat[(size_t)(81 + k) * NPTS + n] = acc;
}

// ---------------- K6: out conv1 (128 x 108) + GN stats ----------------
__global__ void out_conv1_kernel(const float* __restrict__ w1, const float* __restrict__ b1) {
    __shared__ float vt[108][64];
    int n0 = blockIdx.x * 64;
    int o  = threadIdx.x;  // 128
    for (int i = threadIdx.x; i < 108 * 64; i += 128) {
        int c = i / 64, nn = i % 64;
        vt[c][nn] = g_vfeat[(size_t)c * NPTS + n0 + nn];
    }
    __syncthreads();
    float bo = b1[o];
    float lsf = 0.f, ls2f = 0.f;
    for (int nb = 0; nb < 64; nb += 8) {
        float acc[8];
#pragma unroll
        for (int q = 0; q < 8; q++) acc[q] = bo;
        for (int c = 0; c < 108; c++) {
            float wv = __ldg(&w1[o * 108 + c]);
#pragma unroll
            for (int q = 0; q < 8; q++) acc[q] += wv * vt[c][nb + q];
        }
#pragma unroll
        for (int q = 0; q < 8; q++) {
            g_hout[(size_t)o * NPTS + n0 + nb + q] = acc[q];
            lsf  += acc[q];
            ls2f += acc[q] * acc[q];
        }
    }
    atomicAdd(&g_out_sum[o >> 4],  (double)lsf);
    atomicAdd(&g_out_sum2[o >> 4], (double)ls2f);
}

// ---------------- K7: finalize out GN stats ----------------
__global__ void finalize_out_kernel() {
    int t = threadIdx.x;
    if (t < 8) {
        double cnt = 16.0 * NPTS;
        double mu  = g_out_sum[t] / cnt;
        double var = g_out_sum2[t] / cnt - mu * mu;
        g_out_mu[t]  = (float)mu;
        g_out_inv[t] = (float)(1.0 / sqrt(var + 1e-5));
    }
}

// ---------------- K8: out GN+prelu + conv2 (64 x 128) -> d_out ----------------
__global__ void out_apply_kernel(const float* __restrict__ gma, const float* __restrict__ bta,
                                 const float* __restrict__ pr, const float* __restrict__ w2,
                                 const float* __restrict__ b2, float* __restrict__ out) {
    __shared__ float act[128][64];
    int n0 = blockIdx.x * 64;
    int t  = threadIdx.x;  // 256
    float a = pr[0];
    for (int i = t; i < 128 * 64; i += 256) {
        int ch = i / 64, nn = i % 64;
        float x = g_hout[(size_t)ch * NPTS + n0 + nn];
        int gr = ch >> 4;
        x = (x - g_out_mu[gr]) * g_out_inv[gr] * gma[ch] + bta[ch];
        act[ch][nn] = (x >= 0.f) ? x : a * x;
    }
    __syncthreads();
    for (int i = t; i < 64 * 64; i += 256) {
        int o = i / 64, nn = i % 64;
        float acc = b2[o];
        for (int c = 0; c < 128; c++) acc += w2[o * 128 + c] * act[c][nn];
        out[(size_t)o * NPTS + n0 + nn] = acc;
    }
}

// ---------------- K9: knn GN+prelu+max + conv (64x64), add into d_out ----------
__global__ void knn_apply_kernel(const float* __restrict__ w1, const float* __restrict__ b1,
                                 const float* __restrict__ gma, const float* __restrict__ bta,
                                 const float* __restrict__ pr, const float* __restrict__ ow,
                                 const float* __restrict__ ob, float* __restrict__ out) {
    __shared__ float s_kf[64];
    __shared__ float s_kin[KNN][4];
    int n = blockIdx.x;
    int t = threadIdx.x;  // 64
    for (int i = t; i < KNN * 4; i += 64)
        s_kin[i / 4][i % 4] = g_kin[(size_t)n * KNN * 4 + i];
    __syncthreads();
    {
        int ch = t;
        float a = pr[0];
        float w0 = w1[ch * 4 + 0], w1_ = w1[ch * 4 + 1], w2_ = w1[ch * 4 + 2], w3_ = w1[ch * 4 + 3];
        float bb = b1[ch];
        float mu = g_knn_mu[ch >> 3], inv = g_knn_inv[ch >> 3];
        float gg = gma[ch], bt_ = bta[ch];
        float mx = -INFINITY;
#pragma unroll
        for (int s = 0; s < KNN; s++) {
            float h = w0 * s_kin[s][0] + w1_ * s_kin[s][1] + w2_ * s_kin[s][2] + w3_ * s_kin[s][3] + bb;
            h = (h - mu) * inv * gg + bt_;
            h = (h >= 0.f) ? h : a * h;
            mx = fmaxf(mx, h);
        }
        s_kf[ch] = mx;
    }
    __syncthreads();
    {
        int o = t;
        float acc = ob[o];
#pragma unroll
        for (int c = 0; c < 64; c++) acc += ow[o * 64 + c] * s_kf[c];
        out[(size_t)o * NPTS + n] += acc;
    }
}

// ---------------- launch ----------------
extern "C" void kernel_launch(void* const* d_in, const int* in_sizes, int n_in,
                              void* d_out, int out_size) {
    const float* fmap1  = (const float*)d_in[0];
    const float* fmap2  = (const float*)d_in[1];
    const float* xyz2   = (const float*)d_in[2];
    const float* coords = (const float*)d_in[3];
    const float* out_w1 = (const float*)d_in[4];
    const float* out_b1 = (const float*)d_in[5];
    const float* out_g  = (const float*)d_in[6];
    const float* out_bt = (const float*)d_in[7];
    const float* out_pr = (const float*)d_in[8];
    const float* out_w2 = (const float*)d_in[9];
    const float* out_b2 = (const float*)d_in[10];
    const float* vox_w1 = (const float*)d_in[11];
    const float* vox_b1 = (const float*)d_in[12];
    const float* vox_g  = (const float*)d_in[13];
    const float* vox_bt = (const float*)d_in[14];
    const float* vox_pr = (const float*)d_in[15];
    const float* vox_w2 = (const float*)d_in[16];
    const float* vox_b2 = (const float*)d_in[17];
    const float* knn_w1 = (const float*)d_in[18];
    const float* knn_b1 = (const float*)d_in[19];
    const float* knn_g  = (const float*)d_in[20];
    const float* knn_bt = (const float*)d_in[21];
    const float* knn_pr = (const float*)d_in[22];
    const float* knn_ow = (const float*)d_in[23];
    const float* knn_ob = (const float*)d_in[24];
    float* out = (float*)d_out;

    zero_stats_kernel<<<1, 32>>>();
    gemm_corr_kernel<<<dim3(NPTS / GBN, NPTS / GBM), 256>>>(fmap1, fmap2);
    topk_kernel<<<NPTS, 256>>>(xyz2);
    pointfeat_kernel<<<NPTS, 128>>>(coords, vox_w1, vox_b1, knn_w1, knn_b1);
    finalize_vk_kernel<<<1, 32>>>();
    vox_apply_kernel<<<(NPTS * 27 + 255) / 256, 256>>>(vox_w1, vox_b1, vox_g, vox_bt,
                                                       vox_pr, vox_w2, vox_b2);
    out_conv1_kernel<<<NPTS / 64, 128>>>(out_w1, out_b1);
    finalize_out_kernel<<<1, 32>>>();
    out_apply_kernel<<<NPTS / 64, 256>>>(out_g, out_bt, out_pr, out_w2, out_b2, out);
    knn_apply_kernel<<<NPTS, 64>>>(knn_w1, knn_b1, knn_g, knn_bt, knn_pr,
                                   knn_ow, knn_ob, out);
}